// round 1
// baseline (speedup 1.0000x reference)
#include <cuda_runtime.h>
#include <cuda_bf16.h>

// Problem constants (fixed by the reference)
#define NSPEC      16
#define DIMRAD     16
#define DIMRADANG  8
#define NF         5          // NMAX_ANGLE + 1
#define VDIM       2
#define ROW        432        // 16 + 256 + 160
#define RAD_OFF    16
#define ANG_OFF    272
#define MAX_EDGES_ANG 500000

// per-angular-edge valence rows: vedge[e] = valence_table[species[edge_dst_ang[e]]]
__device__ float2 g_vedge[MAX_EDGES_ANG];

// ---------------------------------------------------------------------------
// Kernel 0: zero the output (poisoned to 0xAA by the harness)
// ---------------------------------------------------------------------------
__global__ void zero_kernel(float4* __restrict__ out, int n4) {
    int i = blockIdx.x * blockDim.x + threadIdx.x;
    if (i < n4) out[i] = make_float4(0.f, 0.f, 0.f, 0.f);
}

// ---------------------------------------------------------------------------
// Kernel 1: one-hot block + build per-edge valence table
// ---------------------------------------------------------------------------
__global__ void prep_kernel(float* __restrict__ out,
                            const int* __restrict__ species,
                            const int* __restrict__ edge_dst_ang,
                            const float* __restrict__ vtab,
                            int n_atoms, int n_edges_ang) {
    int i = blockIdx.x * blockDim.x + threadIdx.x;
    if (i < n_atoms) {
        int s = species[i];
        out[(long)i * ROW + s] = 1.0f;
    }
    if (i < n_edges_ang) {
        int a = edge_dst_ang[i];
        int s = species[a];
        g_vedge[i] = make_float2(vtab[s * VDIM + 0], vtab[s * VDIM + 1]);
    }
}

// ---------------------------------------------------------------------------
// Kernel 2: radial AEV. One thread per edge; only the species[dst] column of
// the one-hot is nonzero, so each edge contributes exactly DIMRAD adds.
// ---------------------------------------------------------------------------
__global__ void radial_kernel(float* __restrict__ out,
                              const float* __restrict__ dist,
                              const float* __restrict__ sw,
                              const int*  __restrict__ esrc,
                              const int*  __restrict__ edst,
                              const int*  __restrict__ species,
                              int n_edges) {
    int e = blockIdx.x * blockDim.x + threadIdx.x;
    if (e >= n_edges) return;
    float d = dist[e];
    float s = sw[e];
    int src = esrc[e];
    int sd  = species[edst[e]];

    // gaussian_basis(d, 5.0, 16): centers = r * 5/15, eta = (16/5)^2
    const float step = 5.0f / 15.0f;
    const float eta  = 10.24f;

    float* base = out + (long)src * ROW + RAD_OFF + sd;
    #pragma unroll
    for (int r = 0; r < DIMRAD; r++) {
        float t = d - (float)r * step;
        float v = s * __expf(-eta * t * t);
        atomicAdd(base + r * NSPEC, v);   // offset r*16 + sd within radial block
    }
}

// ---------------------------------------------------------------------------
// Kernel 3: angular AEV. One thread per angle term. 40 x red.global.add.v4.f32
// per angle (inner V*V=4 block is contiguous and 16B-aligned).
// ---------------------------------------------------------------------------
__global__ void angular_kernel(float* __restrict__ out,
                               const float* __restrict__ angles,
                               const float* __restrict__ dang,
                               const float* __restrict__ swang,
                               const int*  __restrict__ central,
                               const int*  __restrict__ asrc,
                               const int*  __restrict__ adst,
                               int n_angles) {
    int t = blockIdx.x * blockDim.x + threadIdx.x;
    if (t >= n_angles) return;

    float ang = angles[t];
    int   c   = central[t];
    int   es  = asrc[t];
    int   ed  = adst[t];

    float ds = dang[es], dd = dang[ed];
    float ss = swang[es], sd = swang[ed];
    float2 vs = g_vedge[es];
    float2 vd = g_vedge[ed];

    float d12  = 0.5f * (ds + dd);
    float sw12 = ss * sd;

    // factor2: gaussian_basis(d12, 3.5, 8): centers = i*0.5, eta = (8/3.5)^2
    const float eta2 = 5.2244897959183673f;
    float f2[DIMRADANG];
    #pragma unroll
    for (int i = 0; i < DIMRADANG; i++) {
        float u = d12 - 0.5f * (float)i;
        f2[i] = __expf(-eta2 * u * u);
    }

    // factor1[f] = cos(f*ang) * sw12 via Chebyshev recurrence
    float f1[NF];
    float ca = __cosf(ang);
    f1[0] = sw12;
    f1[1] = ca * sw12;
    #pragma unroll
    for (int f = 2; f < NF; f++) f1[f] = 2.0f * ca * f1[f - 1] - f1[f - 2];

    // valence outer: j = p*2 + m, vp = vs+vd, vm = vs*vd
    float vp0 = vs.x + vd.x, vp1 = vs.y + vd.y;
    float vm0 = vs.x * vd.x, vm1 = vs.y * vd.y;
    float val0 = vp0 * vm0, val1 = vp0 * vm1;
    float val2 = vp1 * vm0, val3 = vp1 * vm1;

    float* base = out + (long)c * ROW + ANG_OFF;   // 16B-aligned (272%4==0, 432%4==0)
    #pragma unroll
    for (int ra = 0; ra < DIMRADANG; ra++) {
        #pragma unroll
        for (int f = 0; f < NF; f++) {
            float term = f1[f] * f2[ra];
            float x = term * val0, y = term * val1, z = term * val2, w = term * val3;
            float* p = base + (ra * NF + f) * 4;
            asm volatile("red.global.add.v4.f32 [%0], {%1, %2, %3, %4};"
                         :: "l"(p), "f"(x), "f"(y), "f"(z), "f"(w)
                         : "memory");
        }
    }
}

// ---------------------------------------------------------------------------
// Launch
// ---------------------------------------------------------------------------
extern "C" void kernel_launch(void* const* d_in, const int* in_sizes, int n_in,
                              void* d_out, int out_size) {
    const int*   species      = (const int*)  d_in[0];
    const float* distances    = (const float*)d_in[1];
    const float* switch_      = (const float*)d_in[2];
    const int*   edge_src     = (const int*)  d_in[3];
    const int*   edge_dst     = (const int*)  d_in[4];
    const float* angles       = (const float*)d_in[5];
    const float* dang         = (const float*)d_in[6];
    const float* switch_ang   = (const float*)d_in[7];
    const int*   central_atom = (const int*)  d_in[8];
    const int*   angle_src    = (const int*)  d_in[9];
    const int*   angle_dst    = (const int*)  d_in[10];
    const int*   edge_dst_ang = (const int*)  d_in[11];
    const float* valence_tab  = (const float*)d_in[12];

    float* out = (float*)d_out;

    int n_atoms     = in_sizes[0];
    int n_edges     = in_sizes[1];
    int n_angles    = in_sizes[5];
    int n_edges_ang = in_sizes[6];

    // zero output
    int n4 = out_size / 4;
    zero_kernel<<<(n4 + 255) / 256, 256>>>((float4*)out, n4);

    // one-hot + per-edge valence table
    int np = n_atoms > n_edges_ang ? n_atoms : n_edges_ang;
    prep_kernel<<<(np + 255) / 256, 256>>>(out, species, edge_dst_ang,
                                           valence_tab, n_atoms, n_edges_ang);

    // radial scatter
    radial_kernel<<<(n_edges + 255) / 256, 256>>>(out, distances, switch_,
                                                  edge_src, edge_dst, species,
                                                  n_edges);

    // angular scatter
    angular_kernel<<<(n_angles + 255) / 256, 256>>>(out, angles, dang,
                                                    switch_ang, central_atom,
                                                    angle_src, angle_dst,
                                                    n_angles);
}

// round 2
// speedup vs baseline: 1.4649x; 1.4649x over previous
#include <cuda_runtime.h>
#include <cuda_bf16.h>

// Problem constants (fixed by the reference)
#define NSPEC      16
#define DIMRAD     16
#define DIMRADANG  8
#define NF         5          // NMAX_ANGLE + 1
#define VDIM       2
#define ROW        432        // 16 + 256 + 160
#define ROW4       108
#define RAD_OFF    16
#define ANG_OFF    272
#define ANG_OFF4   68
#define MAX_EDGES_ANG 500000
#define MAX_ANGLES    2000000
#define MAX_ATOMS     50000

#define ETA2 5.2244897959183673f   // (8/3.5)^2

// scratch (static __device__ — no runtime allocation)
__device__ float2 g_vedge[MAX_EDGES_ANG];
__device__ int    g_cnt[MAX_ATOMS];
__device__ int    g_off[MAX_ATOMS + 1];
__device__ int    g_cur[MAX_ATOMS];
__device__ float4 g_rec[2 * MAX_ANGLES];   // 64MB: per-angle {d12,ca,sw12,_},{val0..3}

// ---------------------------------------------------------------------------
// Kernel 0: zero onehot+radial columns only (angular block is fully written
// by the accumulate kernel) + zero histogram counters
// ---------------------------------------------------------------------------
__global__ void zero_kernel(float4* __restrict__ out, int n_atoms) {
    int i = blockIdx.x * blockDim.x + threadIdx.x;
    int total = n_atoms * ANG_OFF4;
    if (i < total) {
        int a = i / ANG_OFF4;
        int c = i - a * ANG_OFF4;
        out[a * ROW4 + c] = make_float4(0.f, 0.f, 0.f, 0.f);
    }
    if (i < n_atoms) g_cnt[i] = 0;
}

// ---------------------------------------------------------------------------
// Kernel 1: one-hot + per-angular-edge valence rows
// ---------------------------------------------------------------------------
__global__ void prep_kernel(float* __restrict__ out,
                            const int* __restrict__ species,
                            const int* __restrict__ edge_dst_ang,
                            const float* __restrict__ vtab,
                            int n_atoms, int n_edges_ang) {
    int i = blockIdx.x * blockDim.x + threadIdx.x;
    if (i < n_atoms) {
        int s = species[i];
        out[(long)i * ROW + s] = 1.0f;
    }
    if (i < n_edges_ang) {
        int a = edge_dst_ang[i];
        int s = species[a];
        g_vedge[i] = make_float2(vtab[s * VDIM + 0], vtab[s * VDIM + 1]);
    }
}

// ---------------------------------------------------------------------------
// Kernel 2: histogram of central_atom
// ---------------------------------------------------------------------------
__global__ void hist_kernel(const int* __restrict__ central, int n_angles) {
    int t = blockIdx.x * blockDim.x + threadIdx.x;
    if (t < n_angles) atomicAdd(&g_cnt[central[t]], 1);
}

// ---------------------------------------------------------------------------
// Kernel 3: single-block exclusive scan (shfl warp scans)
// ---------------------------------------------------------------------------
__global__ void scan_kernel(int n) {
    __shared__ int warpsums[32];
    int tid = threadIdx.x, lane = tid & 31, w = tid >> 5;
    int carry = 0;
    for (int base = 0; base < n; base += 1024) {
        int i = base + tid;
        int v = (i < n) ? g_cnt[i] : 0;
        int x = v;
        #pragma unroll
        for (int d = 1; d < 32; d <<= 1) {
            int t = __shfl_up_sync(0xffffffffu, x, d);
            if (lane >= d) x += t;
        }
        if (lane == 31) warpsums[w] = x;
        __syncthreads();
        if (w == 0) {
            int s = warpsums[lane];
            #pragma unroll
            for (int d = 1; d < 32; d <<= 1) {
                int t = __shfl_up_sync(0xffffffffu, s, d);
                if (lane >= d) s += t;
            }
            warpsums[lane] = s;
        }
        __syncthreads();
        int wpre = (w > 0) ? warpsums[w - 1] : 0;
        int excl = carry + x + wpre - v;
        if (i < n) { g_off[i] = excl; g_cur[i] = excl; }
        carry += warpsums[31];
        __syncthreads();
    }
    if (tid == 0) g_off[n] = carry;
}

// ---------------------------------------------------------------------------
// Kernel 4: build per-angle records, scattered into atom-sorted slots
// ---------------------------------------------------------------------------
__global__ void scatter_kernel(const float* __restrict__ angles,
                               const float* __restrict__ dang,
                               const float* __restrict__ swang,
                               const int*  __restrict__ central,
                               const int*  __restrict__ asrc,
                               const int*  __restrict__ adst,
                               int n_angles) {
    int t = blockIdx.x * blockDim.x + threadIdx.x;
    if (t >= n_angles) return;
    int c  = central[t];
    int es = asrc[t];
    int ed = adst[t];
    float ds = dang[es], dd = dang[ed];
    float ss = swang[es], sd = swang[ed];
    float2 vs = g_vedge[es];
    float2 vd = g_vedge[ed];
    float d12  = 0.5f * (ds + dd);
    float sw12 = ss * sd;
    float ca   = __cosf(angles[t]);
    float vp0 = vs.x + vd.x, vp1 = vs.y + vd.y;
    float vm0 = vs.x * vd.x, vm1 = vs.y * vd.y;
    int pos = atomicAdd(&g_cur[c], 1);
    g_rec[2 * pos]     = make_float4(d12, ca, sw12, 0.f);
    g_rec[2 * pos + 1] = make_float4(vp0 * vm0, vp0 * vm1, vp1 * vm0, vp1 * vm1);
}

// ---------------------------------------------------------------------------
// Kernel 5: angular accumulation. One warp per atom; lane owns (ra, v),
// f in [0,5) -> all register indices static, no atomics.
// ---------------------------------------------------------------------------
__global__ void accum_kernel(float* __restrict__ out, int n_atoms) {
    int gw   = (blockIdx.x * blockDim.x + threadIdx.x) >> 5;
    int lane = threadIdx.x & 31;
    if (gw >= n_atoms) return;
    int start = g_off[gw], end = g_off[gw + 1];
    int ra = lane >> 2, v = lane & 3;
    float center = 0.5f * (float)ra;

    float a0 = 0.f, a1 = 0.f, a2 = 0.f, a3 = 0.f, a4 = 0.f;
    const float4* __restrict__ rec = g_rec;
    for (int i = start; i < end; i++) {
        float4 r0 = rec[2 * i];
        float4 r1 = rec[2 * i + 1];
        float d12 = r0.x, ca = r0.y, sw12 = r0.z;
        float val = (v == 0) ? r1.x : (v == 1) ? r1.y : (v == 2) ? r1.z : r1.w;
        float u  = d12 - center;
        float e2 = __expf(-ETA2 * u * u);
        float tt = e2 * val;
        float f0 = sw12;
        float f1 = ca * sw12;
        float c2 = 2.0f * ca;
        float f2 = c2 * f1 - f0;
        float f3 = c2 * f2 - f1;
        float f4 = c2 * f3 - f2;
        a0 = fmaf(f0, tt, a0);
        a1 = fmaf(f1, tt, a1);
        a2 = fmaf(f2, tt, a2);
        a3 = fmaf(f3, tt, a3);
        a4 = fmaf(f4, tt, a4);
    }
    float* base = out + (long)gw * ROW + ANG_OFF + ra * 20 + v;
    base[0]  = a0;
    base[4]  = a1;
    base[8]  = a2;
    base[12] = a3;
    base[16] = a4;
}

// ---------------------------------------------------------------------------
// Kernel 6: radial AEV (unchanged: 16 scalar atomics per edge)
// ---------------------------------------------------------------------------
__global__ void radial_kernel(float* __restrict__ out,
                              const float* __restrict__ dist,
                              const float* __restrict__ sw,
                              const int*  __restrict__ esrc,
                              const int*  __restrict__ edst,
                              const int*  __restrict__ species,
                              int n_edges) {
    int e = blockIdx.x * blockDim.x + threadIdx.x;
    if (e >= n_edges) return;
    float d = dist[e];
    float s = sw[e];
    int src = esrc[e];
    int sd  = species[edst[e]];
    const float step = 5.0f / 15.0f;
    const float eta  = 10.24f;
    float* base = out + (long)src * ROW + RAD_OFF + sd;
    #pragma unroll
    for (int r = 0; r < DIMRAD; r++) {
        float t = d - (float)r * step;
        float v = s * __expf(-eta * t * t);
        atomicAdd(base + r * NSPEC, v);
    }
}

// ---------------------------------------------------------------------------
// Launch
// ---------------------------------------------------------------------------
extern "C" void kernel_launch(void* const* d_in, const int* in_sizes, int n_in,
                              void* d_out, int out_size) {
    const int*   species      = (const int*)  d_in[0];
    const float* distances    = (const float*)d_in[1];
    const float* switch_      = (const float*)d_in[2];
    const int*   edge_src     = (const int*)  d_in[3];
    const int*   edge_dst     = (const int*)  d_in[4];
    const float* angles       = (const float*)d_in[5];
    const float* dang         = (const float*)d_in[6];
    const float* switch_ang   = (const float*)d_in[7];
    const int*   central_atom = (const int*)  d_in[8];
    const int*   angle_src    = (const int*)  d_in[9];
    const int*   angle_dst    = (const int*)  d_in[10];
    const int*   edge_dst_ang = (const int*)  d_in[11];
    const float* valence_tab  = (const float*)d_in[12];

    float* out = (float*)d_out;

    int n_atoms     = in_sizes[0];
    int n_edges     = in_sizes[1];
    int n_angles    = in_sizes[5];
    int n_edges_ang = in_sizes[6];

    // zero onehot+radial region + counters
    int nz = n_atoms * ANG_OFF4;
    zero_kernel<<<(nz + 255) / 256, 256>>>((float4*)out, n_atoms);

    // one-hot + per-edge valence table
    int np = n_atoms > n_edges_ang ? n_atoms : n_edges_ang;
    prep_kernel<<<(np + 255) / 256, 256>>>(out, species, edge_dst_ang,
                                           valence_tab, n_atoms, n_edges_ang);

    // CSR build for angular
    hist_kernel<<<(n_angles + 255) / 256, 256>>>(central_atom, n_angles);
    scan_kernel<<<1, 1024>>>(n_atoms);
    scatter_kernel<<<(n_angles + 255) / 256, 256>>>(angles, dang, switch_ang,
                                                    central_atom, angle_src,
                                                    angle_dst, n_angles);

    // radial scatter (independent of angular pipeline)
    radial_kernel<<<(n_edges + 255) / 256, 256>>>(out, distances, switch_,
                                                  edge_src, edge_dst, species,
                                                  n_edges);

    // angular accumulation: one warp per atom
    int nt = n_atoms * 32;
    accum_kernel<<<(nt + 255) / 256, 256>>>(out, n_atoms);
}

// round 3
// speedup vs baseline: 2.0426x; 1.3943x over previous
#include <cuda_runtime.h>
#include <cuda_bf16.h>

// Problem constants (fixed by the reference)
#define NSPEC      16
#define DIMRAD     16
#define DIMRADANG  8
#define NF         5          // NMAX_ANGLE + 1
#define VDIM       2
#define ROW        432        // 16 + 256 + 160
#define RAD_OFF    16
#define ANG_OFF    272
#define MAX_EDGES      1000000
#define MAX_EDGES_ANG  500000
#define MAX_ANGLES     2000000
#define MAX_ATOMS      50000
#define NB_MAX         64      // scan blocks per array (50000/1024 = 49)

#define ETA_R  10.24f               // (16/5)^2
#define STEP_R 0.33333333333333333f // 5/15
#define ETA2   5.2244897959183673f  // (8/3.5)^2

// scratch (static __device__ — no runtime allocation)
__device__ float2 g_vedge[MAX_EDGES_ANG];
__device__ int    g_cnt[2][MAX_ATOMS];       // [0]=angular(central), [1]=radial(src)
__device__ int    g_scan[2][MAX_ATOMS];
__device__ int    g_psum[2][NB_MAX];
__device__ int    g_psum_ex[2][NB_MAX];
__device__ int    g_off[2][MAX_ATOMS + 1];
__device__ int    g_cur[2][MAX_ATOMS];
__device__ float4 g_arec[2 * MAX_ANGLES];    // angular records: {d12,ca,sw12,_},{val0..3}
__device__ float4 g_rrec[MAX_EDGES];         // radial records:  {d, sw, sd_bits, _}

// ---------------------------------------------------------------------------
// K1: zero one-hot block, set one-hot, zero counters, build per-edge valence
// ---------------------------------------------------------------------------
__global__ void prep_kernel(float* __restrict__ out,
                            const int* __restrict__ species,
                            const int* __restrict__ edge_dst_ang,
                            const float* __restrict__ vtab,
                            int n_atoms, int n_edges_ang) {
    int i = blockIdx.x * blockDim.x + threadIdx.x;
    if (i < n_atoms) {
        float4* p = (float4*)(out + (long)i * ROW);
        float4 z = make_float4(0.f, 0.f, 0.f, 0.f);
        p[0] = z; p[1] = z; p[2] = z; p[3] = z;
        out[(long)i * ROW + species[i]] = 1.0f;
        g_cnt[0][i] = 0;
        g_cnt[1][i] = 0;
    }
    if (i < n_edges_ang) {
        int s = species[edge_dst_ang[i]];
        g_vedge[i] = make_float2(vtab[s * VDIM + 0], vtab[s * VDIM + 1]);
    }
}

// ---------------------------------------------------------------------------
// K2: both histograms
// ---------------------------------------------------------------------------
__global__ void hist_kernel(const int* __restrict__ central,
                            const int* __restrict__ esrc,
                            int n_angles, int n_edges) {
    int t = blockIdx.x * blockDim.x + threadIdx.x;
    if (t < n_angles) atomicAdd(&g_cnt[0][central[t]], 1);
    if (t < n_edges)  atomicAdd(&g_cnt[1][esrc[t]], 1);
}

// ---------------------------------------------------------------------------
// K3/K4/K5: three-phase scan (both arrays at once via blockIdx.y)
// ---------------------------------------------------------------------------
__global__ void scan1_kernel(int n) {
    __shared__ int ws[32];
    int arr  = blockIdx.y;
    int i    = blockIdx.x * 1024 + threadIdx.x;
    int lane = threadIdx.x & 31, w = threadIdx.x >> 5;
    int v = (i < n) ? g_cnt[arr][i] : 0;
    int x = v;
    #pragma unroll
    for (int d = 1; d < 32; d <<= 1) {
        int t = __shfl_up_sync(0xffffffffu, x, d);
        if (lane >= d) x += t;
    }
    if (lane == 31) ws[w] = x;
    __syncthreads();
    if (w == 0) {
        int s = ws[lane];
        #pragma unroll
        for (int d = 1; d < 32; d <<= 1) {
            int t = __shfl_up_sync(0xffffffffu, s, d);
            if (lane >= d) s += t;
        }
        ws[lane] = s;
    }
    __syncthreads();
    int incl = x + (w ? ws[w - 1] : 0);
    if (i < n) g_scan[arr][i] = incl;
    if (threadIdx.x == 1023) g_psum[arr][blockIdx.x] = incl;
}

__global__ void scan2_kernel(int nb, int n) {
    __shared__ int s[2][NB_MAX];
    int t = threadIdx.x;               // 128 threads
    int arr = t >> 6, j = t & 63;
    int v = (j < nb) ? g_psum[arr][j] : 0;
    s[arr][j] = v;
    __syncthreads();
    #pragma unroll
    for (int d = 1; d < NB_MAX; d <<= 1) {
        int val = (j >= d) ? s[arr][j - d] : 0;
        __syncthreads();
        s[arr][j] += val;
        __syncthreads();
    }
    g_psum_ex[arr][j] = s[arr][j] - v;
    if (j == NB_MAX - 1) g_off[arr][n] = s[arr][NB_MAX - 1];
}

__global__ void scan3_kernel(int n) {
    int arr = blockIdx.y;
    int i = blockIdx.x * blockDim.x + threadIdx.x;
    if (i < n) {
        int off = g_scan[arr][i] - g_cnt[arr][i] + g_psum_ex[arr][i >> 10];
        g_off[arr][i] = off;
        g_cur[arr][i] = off;
    }
}

// ---------------------------------------------------------------------------
// K6: build records for both CSRs (sorted-by-owner slots)
// ---------------------------------------------------------------------------
__global__ void scatter_kernel(const float* __restrict__ angles,
                               const float* __restrict__ dang,
                               const float* __restrict__ swang,
                               const int*  __restrict__ central,
                               const int*  __restrict__ asrc,
                               const int*  __restrict__ adst,
                               const float* __restrict__ dist,
                               const float* __restrict__ sw,
                               const int*  __restrict__ esrc,
                               const int*  __restrict__ edst,
                               const int*  __restrict__ species,
                               int n_angles, int n_edges) {
    int t = blockIdx.x * blockDim.x + threadIdx.x;
    if (t < n_angles) {
        int es = asrc[t], ed = adst[t];
        float d12  = 0.5f * (dang[es] + dang[ed]);
        float sw12 = swang[es] * swang[ed];
        float ca   = __cosf(angles[t]);
        float2 vs = g_vedge[es];
        float2 vd = g_vedge[ed];
        float vp0 = vs.x + vd.x, vp1 = vs.y + vd.y;
        float vm0 = vs.x * vd.x, vm1 = vs.y * vd.y;
        int pos = atomicAdd(&g_cur[0][central[t]], 1);
        g_arec[2 * pos]     = make_float4(d12, ca, sw12, 0.f);
        g_arec[2 * pos + 1] = make_float4(vp0 * vm0, vp0 * vm1, vp1 * vm0, vp1 * vm1);
    }
    if (t < n_edges) {
        float d = dist[t], s = sw[t];
        int sd = species[edst[t]];
        int pos = atomicAdd(&g_cur[1][esrc[t]], 1);
        g_rrec[pos] = make_float4(d, s, __int_as_float(sd), 0.f);
    }
}

// ---------------------------------------------------------------------------
// K7: fused accumulation. One warp per atom; does radial (smem, conflict-free)
// then angular (registers). No atomics anywhere.
// ---------------------------------------------------------------------------
__global__ void accum_kernel(float* __restrict__ out, int n_atoms) {
    __shared__ float sacc[8][2][16 * 17];   // per-warp, per-half-warp buffers
    int w    = threadIdx.x >> 5;
    int lane = threadIdx.x & 31;
    int atom = blockIdx.x * 8 + w;
    if (atom >= n_atoms) return;

    // ---- radial: half-warp hw owns buffer hw; 16 lanes = 16 radial centers
    float* mybuf = &sacc[w][0][0];
    for (int k = lane; k < 2 * 16 * 17; k += 32) mybuf[k] = 0.f;
    __syncwarp();

    int hw = lane >> 4, lr = lane & 15;
    float ctr = STEP_R * (float)lr;
    float* hbuf = &sacc[w][hw][0];
    {
        int s0 = g_off[1][atom], e0 = g_off[1][atom + 1];
        for (int i = s0 + hw; i < e0; i += 2) {
            float4 r = g_rrec[i];
            int sd = __float_as_int(r.z);
            float u = r.x - ctr;
            float v = r.y * __expf(-ETA_R * u * u);
            hbuf[lr * 17 + sd] += v;
        }
    }
    __syncwarp();
    {
        float* obase = out + (long)atom * ROW + RAD_OFF;
        #pragma unroll
        for (int k = 0; k < 8; k++) {
            int idx = k * 32 + lane;          // coalesced
            int r = idx >> 4, s = idx & 15;
            obase[idx] = sacc[w][0][r * 17 + s] + sacc[w][1][r * 17 + s];
        }
    }

    // ---- angular: lane owns (ra = lane>>2, v = lane&3), f in [0,5) static
    int ra = lane >> 2, v = lane & 3;
    float center = 0.5f * (float)ra;
    float a0 = 0.f, a1 = 0.f, a2 = 0.f, a3 = 0.f, a4 = 0.f;
    int s1 = g_off[0][atom], e1 = g_off[0][atom + 1];
    const float4* __restrict__ rec = g_arec;
    for (int i = s1; i < e1; i++) {
        float4 r0 = rec[2 * i];
        float4 r1 = rec[2 * i + 1];
        float d12 = r0.x, ca = r0.y, sw12 = r0.z;
        float val = (v == 0) ? r1.x : (v == 1) ? r1.y : (v == 2) ? r1.z : r1.w;
        float u  = d12 - center;
        float e2 = __expf(-ETA2 * u * u);
        float tt = e2 * val;
        float f0 = sw12;
        float f1 = ca * sw12;
        float c2 = 2.0f * ca;
        float f2 = c2 * f1 - f0;
        float f3 = c2 * f2 - f1;
        float f4 = c2 * f3 - f2;
        a0 = fmaf(f0, tt, a0);
        a1 = fmaf(f1, tt, a1);
        a2 = fmaf(f2, tt, a2);
        a3 = fmaf(f3, tt, a3);
        a4 = fmaf(f4, tt, a4);
    }
    float* base = out + (long)atom * ROW + ANG_OFF + ra * 20 + v;
    base[0]  = a0;
    base[4]  = a1;
    base[8]  = a2;
    base[12] = a3;
    base[16] = a4;
}

// ---------------------------------------------------------------------------
// Launch
// ---------------------------------------------------------------------------
extern "C" void kernel_launch(void* const* d_in, const int* in_sizes, int n_in,
                              void* d_out, int out_size) {
    const int*   species      = (const int*)  d_in[0];
    const float* distances    = (const float*)d_in[1];
    const float* switch_      = (const float*)d_in[2];
    const int*   edge_src     = (const int*)  d_in[3];
    const int*   edge_dst     = (const int*)  d_in[4];
    const float* angles       = (const float*)d_in[5];
    const float* dang         = (const float*)d_in[6];
    const float* switch_ang   = (const float*)d_in[7];
    const int*   central_atom = (const int*)  d_in[8];
    const int*   angle_src    = (const int*)  d_in[9];
    const int*   angle_dst    = (const int*)  d_in[10];
    const int*   edge_dst_ang = (const int*)  d_in[11];
    const float* valence_tab  = (const float*)d_in[12];

    float* out = (float*)d_out;

    int n_atoms     = in_sizes[0];
    int n_edges     = in_sizes[1];
    int n_angles    = in_sizes[5];
    int n_edges_ang = in_sizes[6];

    // K1: prep
    int np = n_atoms > n_edges_ang ? n_atoms : n_edges_ang;
    prep_kernel<<<(np + 255) / 256, 256>>>(out, species, edge_dst_ang,
                                           valence_tab, n_atoms, n_edges_ang);

    // K2: histograms
    int nh = n_angles > n_edges ? n_angles : n_edges;
    hist_kernel<<<(nh + 255) / 256, 256>>>(central_atom, edge_src,
                                           n_angles, n_edges);

    // K3-K5: scans
    int nb = (n_atoms + 1023) / 1024;
    dim3 g1(nb, 2);
    scan1_kernel<<<g1, 1024>>>(n_atoms);
    scan2_kernel<<<1, 128>>>(nb, n_atoms);
    dim3 g3((n_atoms + 255) / 256, 2);
    scan3_kernel<<<g3, 256>>>(n_atoms);

    // K6: scatter records
    int ns = n_angles > n_edges ? n_angles : n_edges;
    scatter_kernel<<<(ns + 255) / 256, 256>>>(angles, dang, switch_ang,
                                              central_atom, angle_src, angle_dst,
                                              distances, switch_, edge_src,
                                              edge_dst, species,
                                              n_angles, n_edges);

    // K7: fused accumulation (one warp per atom)
    accum_kernel<<<(n_atoms + 7) / 8, 256>>>(out, n_atoms);
}

// round 5
// speedup vs baseline: 2.3826x; 1.1665x over previous
#include <cuda_runtime.h>
#include <cuda_bf16.h>

// Problem constants (fixed by the reference)
#define NSPEC      16
#define DIMRAD     16
#define DIMRADANG  8
#define NF         5          // NMAX_ANGLE + 1
#define VDIM       2
#define ROW        432        // 16 + 256 + 160
#define RAD_OFF    16
#define ANG_OFF    272
#define MAX_EDGES      1000000
#define MAX_EDGES_ANG  500000
#define MAX_ANGLES     2000000
#define MAX_ATOMS      50000
#define NB_MAX         64

#define ETA_R  10.24f               // (16/5)^2
#define STEP_R 0.33333333333333333f // 5/15
#define ETA2   5.2244897959183673f  // (8/3.5)^2

// scratch (static __device__ — no runtime allocation)
__device__ float4 g_eang[MAX_EDGES_ANG];     // {d, sw, v0, v1} per angular edge
__device__ int    g_cnt[2][MAX_ATOMS];       // [0]=angular(central), [1]=radial(src)
__device__ int    g_scan[2][MAX_ATOMS];
__device__ int    g_psum[2][NB_MAX];
__device__ int    g_psum_ex[2][NB_MAX];
__device__ int    g_off[2][MAX_ATOMS + 1];
__device__ int    g_cur[2][MAX_ATOMS];
__device__ float4 g_arec[2 * MAX_ANGLES];    // {d12,ca,sw12,_},{val0..3}
__device__ float4 g_rrec[MAX_EDGES];         // {d, sw, sd_bits, _}

// ---------------------------------------------------------------------------
// K0: zero the histogram counters (MUST precede the histogram kernel —
// zero+atomicAdd in one launch races across blocks).
// ---------------------------------------------------------------------------
__global__ void zero_cnt_kernel(int n_atoms) {
    int i = blockIdx.x * blockDim.x + threadIdx.x;
    if (i < n_atoms) {
        g_cnt[0][i] = 0;
        g_cnt[1][i] = 0;
    }
}

// ---------------------------------------------------------------------------
// K1: prep (one-hot, packed angular-edge table) + both histograms, fused.
// ---------------------------------------------------------------------------
__global__ void prep_hist_kernel(float* __restrict__ out,
                                 const int* __restrict__ species,
                                 const int* __restrict__ edge_dst_ang,
                                 const float* __restrict__ vtab,
                                 const float* __restrict__ dang,
                                 const float* __restrict__ swang,
                                 const int* __restrict__ central,
                                 const int* __restrict__ esrc,
                                 int n_atoms, int n_edges_ang,
                                 int n_angles, int n_edges) {
    int i = blockIdx.x * blockDim.x + threadIdx.x;
    if (i < n_atoms) {
        float4* p = (float4*)(out + (long)i * ROW);
        float4 z = make_float4(0.f, 0.f, 0.f, 0.f);
        p[0] = z; p[1] = z; p[2] = z; p[3] = z;
        out[(long)i * ROW + species[i]] = 1.0f;
    }
    if (i < n_edges_ang) {
        int s = species[edge_dst_ang[i]];
        g_eang[i] = make_float4(dang[i], swang[i],
                                vtab[s * VDIM + 0], vtab[s * VDIM + 1]);
    }
    if (i < n_angles) atomicAdd(&g_cnt[0][central[i]], 1);
    if (i < n_edges)  atomicAdd(&g_cnt[1][esrc[i]], 1);
}

// ---------------------------------------------------------------------------
// K2/K3/K4: three-phase scan (both arrays via blockIdx.y)
// ---------------------------------------------------------------------------
__global__ void scan1_kernel(int n) {
    __shared__ int ws[32];
    int arr  = blockIdx.y;
    int i    = blockIdx.x * 1024 + threadIdx.x;
    int lane = threadIdx.x & 31, w = threadIdx.x >> 5;
    int v = (i < n) ? g_cnt[arr][i] : 0;
    int x = v;
    #pragma unroll
    for (int d = 1; d < 32; d <<= 1) {
        int t = __shfl_up_sync(0xffffffffu, x, d);
        if (lane >= d) x += t;
    }
    if (lane == 31) ws[w] = x;
    __syncthreads();
    if (w == 0) {
        int s = ws[lane];
        #pragma unroll
        for (int d = 1; d < 32; d <<= 1) {
            int t = __shfl_up_sync(0xffffffffu, s, d);
            if (lane >= d) s += t;
        }
        ws[lane] = s;
    }
    __syncthreads();
    int incl = x + (w ? ws[w - 1] : 0);
    if (i < n) g_scan[arr][i] = incl;
    if (threadIdx.x == 1023) g_psum[arr][blockIdx.x] = incl;
}

__global__ void scan2_kernel(int nb, int n) {
    __shared__ int s[2][NB_MAX];
    int t = threadIdx.x;               // 128 threads
    int arr = t >> 6, j = t & 63;
    int v = (j < nb) ? g_psum[arr][j] : 0;
    s[arr][j] = v;
    __syncthreads();
    #pragma unroll
    for (int d = 1; d < NB_MAX; d <<= 1) {
        int val = (j >= d) ? s[arr][j - d] : 0;
        __syncthreads();
        s[arr][j] += val;
        __syncthreads();
    }
    g_psum_ex[arr][j] = s[arr][j] - v;
    if (j == NB_MAX - 1) g_off[arr][n] = s[arr][NB_MAX - 1];
}

__global__ void scan3_kernel(int n) {
    int arr = blockIdx.y;
    int i = blockIdx.x * blockDim.x + threadIdx.x;
    if (i < n) {
        int off = g_scan[arr][i] - g_cnt[arr][i] + g_psum_ex[arr][i >> 10];
        g_off[arr][i] = off;
        g_cur[arr][i] = off;
    }
}

// ---------------------------------------------------------------------------
// K5: build records for both CSRs. Angular: 2 packed 16B gathers per angle.
// ---------------------------------------------------------------------------
__global__ void scatter_kernel(const float* __restrict__ angles,
                               const int*  __restrict__ central,
                               const int*  __restrict__ asrc,
                               const int*  __restrict__ adst,
                               const float* __restrict__ dist,
                               const float* __restrict__ sw,
                               const int*  __restrict__ esrc,
                               const int*  __restrict__ edst,
                               const int*  __restrict__ species,
                               int n_angles, int n_edges) {
    int t = blockIdx.x * blockDim.x + threadIdx.x;
    if (t < n_angles) {
        int es = asrc[t], ed = adst[t];
        float4 ps = g_eang[es];
        float4 pd = g_eang[ed];
        float d12  = 0.5f * (ps.x + pd.x);
        float sw12 = ps.y * pd.y;
        float ca   = __cosf(angles[t]);
        float vp0 = ps.z + pd.z, vp1 = ps.w + pd.w;
        float vm0 = ps.z * pd.z, vm1 = ps.w * pd.w;
        int pos = atomicAdd(&g_cur[0][central[t]], 1);
        g_arec[2 * pos]     = make_float4(d12, ca, sw12, 0.f);
        g_arec[2 * pos + 1] = make_float4(vp0 * vm0, vp0 * vm1, vp1 * vm0, vp1 * vm1);
    }
    if (t < n_edges) {
        float d = dist[t], s = sw[t];
        int sd = species[edst[t]];
        int pos = atomicAdd(&g_cur[1][esrc[t]], 1);
        g_rrec[pos] = make_float4(d, s, __int_as_float(sd), 0.f);
    }
}

// ---------------------------------------------------------------------------
// K6: fused accumulation. One warp per atom: radial in smem (conflict-free),
// angular in registers (static indices per lane). No atomics.
// ---------------------------------------------------------------------------
__global__ void accum_kernel(float* __restrict__ out, int n_atoms) {
    __shared__ float sacc[8][2][16 * 17];
    int w    = threadIdx.x >> 5;
    int lane = threadIdx.x & 31;
    int atom = blockIdx.x * 8 + w;
    if (atom >= n_atoms) return;

    // ---- radial
    float* mybuf = &sacc[w][0][0];
    for (int k = lane; k < 2 * 16 * 17; k += 32) mybuf[k] = 0.f;
    __syncwarp();

    int hw = lane >> 4, lr = lane & 15;
    float ctr = STEP_R * (float)lr;
    float* hbuf = &sacc[w][hw][0];
    {
        int s0 = g_off[1][atom], e0 = g_off[1][atom + 1];
        for (int i = s0 + hw; i < e0; i += 2) {
            float4 r = g_rrec[i];
            int sd = __float_as_int(r.z);
            float u = r.x - ctr;
            float v = r.y * __expf(-ETA_R * u * u);
            hbuf[lr * 17 + sd] += v;
        }
    }
    __syncwarp();
    {
        float* obase = out + (long)atom * ROW + RAD_OFF;
        #pragma unroll
        for (int k = 0; k < 8; k++) {
            int idx = k * 32 + lane;          // coalesced
            int r = idx >> 4, s = idx & 15;
            obase[idx] = sacc[w][0][r * 17 + s] + sacc[w][1][r * 17 + s];
        }
    }

    // ---- angular: lane owns (ra = lane>>2, v = lane&3), unrolled x2
    int ra = lane >> 2, v = lane & 3;
    float center = 0.5f * (float)ra;
    float a0 = 0.f, a1 = 0.f, a2 = 0.f, a3 = 0.f, a4 = 0.f;
    int s1 = g_off[0][atom], e1 = g_off[0][atom + 1];
    const float4* __restrict__ rec = g_arec;

    int i = s1;
    for (; i + 2 <= e1; i += 2) {
        float4 p0 = rec[2 * i];
        float4 p1 = rec[2 * i + 1];
        float4 q0 = rec[2 * i + 2];
        float4 q1 = rec[2 * i + 3];
        {
            float val = (v == 0) ? p1.x : (v == 1) ? p1.y : (v == 2) ? p1.z : p1.w;
            float u  = p0.x - center;
            float tt = __expf(-ETA2 * u * u) * val;
            float f0 = p0.z;
            float f1 = p0.y * p0.z;
            float c2 = 2.0f * p0.y;
            float f2 = c2 * f1 - f0;
            float f3 = c2 * f2 - f1;
            float f4 = c2 * f3 - f2;
            a0 = fmaf(f0, tt, a0); a1 = fmaf(f1, tt, a1); a2 = fmaf(f2, tt, a2);
            a3 = fmaf(f3, tt, a3); a4 = fmaf(f4, tt, a4);
        }
        {
            float val = (v == 0) ? q1.x : (v == 1) ? q1.y : (v == 2) ? q1.z : q1.w;
            float u  = q0.x - center;
            float tt = __expf(-ETA2 * u * u) * val;
            float f0 = q0.z;
            float f1 = q0.y * q0.z;
            float c2 = 2.0f * q0.y;
            float f2 = c2 * f1 - f0;
            float f3 = c2 * f2 - f1;
            float f4 = c2 * f3 - f2;
            a0 = fmaf(f0, tt, a0); a1 = fmaf(f1, tt, a1); a2 = fmaf(f2, tt, a2);
            a3 = fmaf(f3, tt, a3); a4 = fmaf(f4, tt, a4);
        }
    }
    for (; i < e1; i++) {
        float4 p0 = rec[2 * i];
        float4 p1 = rec[2 * i + 1];
        float val = (v == 0) ? p1.x : (v == 1) ? p1.y : (v == 2) ? p1.z : p1.w;
        float u  = p0.x - center;
        float tt = __expf(-ETA2 * u * u) * val;
        float f0 = p0.z;
        float f1 = p0.y * p0.z;
        float c2 = 2.0f * p0.y;
        float f2 = c2 * f1 - f0;
        float f3 = c2 * f2 - f1;
        float f4 = c2 * f3 - f2;
        a0 = fmaf(f0, tt, a0); a1 = fmaf(f1, tt, a1); a2 = fmaf(f2, tt, a2);
        a3 = fmaf(f3, tt, a3); a4 = fmaf(f4, tt, a4);
    }

    float* base = out + (long)atom * ROW + ANG_OFF + ra * 20 + v;
    base[0]  = a0;
    base[4]  = a1;
    base[8]  = a2;
    base[12] = a3;
    base[16] = a4;
}

// ---------------------------------------------------------------------------
// Launch
// ---------------------------------------------------------------------------
extern "C" void kernel_launch(void* const* d_in, const int* in_sizes, int n_in,
                              void* d_out, int out_size) {
    const int*   species      = (const int*)  d_in[0];
    const float* distances    = (const float*)d_in[1];
    const float* switch_      = (const float*)d_in[2];
    const int*   edge_src     = (const int*)  d_in[3];
    const int*   edge_dst     = (const int*)  d_in[4];
    const float* angles       = (const float*)d_in[5];
    const float* dang         = (const float*)d_in[6];
    const float* switch_ang   = (const float*)d_in[7];
    const int*   central_atom = (const int*)  d_in[8];
    const int*   angle_src    = (const int*)  d_in[9];
    const int*   angle_dst    = (const int*)  d_in[10];
    const int*   edge_dst_ang = (const int*)  d_in[11];
    const float* valence_tab  = (const float*)d_in[12];

    float* out = (float*)d_out;

    int n_atoms     = in_sizes[0];
    int n_edges     = in_sizes[1];
    int n_angles    = in_sizes[5];
    int n_edges_ang = in_sizes[6];

    // K0: zero counters (separate launch — avoids zero/atomic race)
    zero_cnt_kernel<<<(n_atoms + 255) / 256, 256>>>(n_atoms);

    // K1: prep + histograms (fused)
    int n1 = n_angles > n_edges ? n_angles : n_edges;
    prep_hist_kernel<<<(n1 + 255) / 256, 256>>>(out, species, edge_dst_ang,
                                                valence_tab, dang, switch_ang,
                                                central_atom, edge_src,
                                                n_atoms, n_edges_ang,
                                                n_angles, n_edges);

    // K2-K4: scans
    int nb = (n_atoms + 1023) / 1024;
    dim3 g1(nb, 2);
    scan1_kernel<<<g1, 1024>>>(n_atoms);
    scan2_kernel<<<1, 128>>>(nb, n_atoms);
    dim3 g3((n_atoms + 255) / 256, 2);
    scan3_kernel<<<g3, 256>>>(n_atoms);

    // K5: scatter records
    scatter_kernel<<<(n1 + 255) / 256, 256>>>(angles, central_atom,
                                              angle_src, angle_dst,
                                              distances, switch_, edge_src,
                                              edge_dst, species,
                                              n_angles, n_edges);

    // K6: fused accumulation (one warp per atom)
    accum_kernel<<<(n_atoms + 7) / 8, 256>>>(out, n_atoms);
}

// round 6
// speedup vs baseline: 3.0299x; 1.2717x over previous
#include <cuda_runtime.h>
#include <cuda_bf16.h>
#include <cuda_fp16.h>

// Problem constants (fixed by the reference)
#define NSPEC      16
#define DIMRAD     16
#define DIMRADANG  8
#define NF         5          // NMAX_ANGLE + 1
#define VDIM       2
#define ROW        432        // 16 + 256 + 160
#define RAD_OFF    16
#define ANG_OFF    272
#define MAX_EDGES      1000000
#define MAX_EDGES_ANG  500000
#define MAX_ANGLES     2000000
#define MAX_ATOMS      50000
#define NB_MAX         64

#define ETA_R  10.24f               // (16/5)^2
#define STEP_R 0.33333333333333333f // 5/15
#define ETA2   5.2244897959183673f  // (8/3.5)^2

// scratch (static __device__ — zero-initialized at module load, no runtime alloc)
__device__ float4 g_eang[MAX_EDGES_ANG];     // {d, sw, v0, v1} per angular edge
__device__ int    g_cnt[2][MAX_ATOMS];       // [0]=angular(central), [1]=radial(src)
                                             // invariant: zero at kernel_launch entry
__device__ int    g_scan[2][MAX_ATOMS];
__device__ int    g_psum[2][NB_MAX];
__device__ int    g_psum_ex[2][NB_MAX];
__device__ int    g_off[2][MAX_ATOMS + 1];
__device__ int    g_cur[2][MAX_ATOMS];
__device__ float4 g_arec[MAX_ANGLES];        // {d12, ca, half2(val0,val1), half2(val2,val3)}
__device__ float2 g_rrec[MAX_EDGES];         // {d, (float)sd + sw}

// ---------------------------------------------------------------------------
// K1: prep (one-hot, packed angular-edge table) + both histograms, fused.
// g_cnt is guaranteed zero on entry (zeroed by scan3 of the previous call,
// zero-init on the first call).
// ---------------------------------------------------------------------------
__global__ void prep_hist_kernel(float* __restrict__ out,
                                 const int* __restrict__ species,
                                 const int* __restrict__ edge_dst_ang,
                                 const float* __restrict__ vtab,
                                 const float* __restrict__ dang,
                                 const float* __restrict__ swang,
                                 const int* __restrict__ central,
                                 const int* __restrict__ esrc,
                                 int n_atoms, int n_edges_ang,
                                 int n_angles, int n_edges) {
    int i = blockIdx.x * blockDim.x + threadIdx.x;
    if (i < n_atoms) {
        float4* p = (float4*)(out + (long)i * ROW);
        float4 z = make_float4(0.f, 0.f, 0.f, 0.f);
        p[0] = z; p[1] = z; p[2] = z; p[3] = z;
        out[(long)i * ROW + species[i]] = 1.0f;
    }
    if (i < n_edges_ang) {
        int s = species[edge_dst_ang[i]];
        g_eang[i] = make_float4(dang[i], swang[i],
                                vtab[s * VDIM + 0], vtab[s * VDIM + 1]);
    }
    if (i < n_angles) atomicAdd(&g_cnt[0][central[i]], 1);
    if (i < n_edges)  atomicAdd(&g_cnt[1][esrc[i]], 1);
}

// ---------------------------------------------------------------------------
// K2/K3/K4: three-phase scan (both arrays via blockIdx.y)
// ---------------------------------------------------------------------------
__global__ void scan1_kernel(int n) {
    __shared__ int ws[32];
    int arr  = blockIdx.y;
    int i    = blockIdx.x * 1024 + threadIdx.x;
    int lane = threadIdx.x & 31, w = threadIdx.x >> 5;
    int v = (i < n) ? g_cnt[arr][i] : 0;
    int x = v;
    #pragma unroll
    for (int d = 1; d < 32; d <<= 1) {
        int t = __shfl_up_sync(0xffffffffu, x, d);
        if (lane >= d) x += t;
    }
    if (lane == 31) ws[w] = x;
    __syncthreads();
    if (w == 0) {
        int s = ws[lane];
        #pragma unroll
        for (int d = 1; d < 32; d <<= 1) {
            int t = __shfl_up_sync(0xffffffffu, s, d);
            if (lane >= d) s += t;
        }
        ws[lane] = s;
    }
    __syncthreads();
    int incl = x + (w ? ws[w - 1] : 0);
    if (i < n) g_scan[arr][i] = incl;
    if (threadIdx.x == 1023) g_psum[arr][blockIdx.x] = incl;
}

__global__ void scan2_kernel(int nb, int n) {
    __shared__ int s[2][NB_MAX];
    int t = threadIdx.x;               // 128 threads
    int arr = t >> 6, j = t & 63;
    int v = (j < nb) ? g_psum[arr][j] : 0;
    s[arr][j] = v;
    __syncthreads();
    #pragma unroll
    for (int d = 1; d < NB_MAX; d <<= 1) {
        int val = (j >= d) ? s[arr][j - d] : 0;
        __syncthreads();
        s[arr][j] += val;
        __syncthreads();
    }
    g_psum_ex[arr][j] = s[arr][j] - v;
    if (j == NB_MAX - 1) g_off[arr][n] = s[arr][NB_MAX - 1];
}

__global__ void scan3_kernel(int n) {
    int arr = blockIdx.y;
    int i = blockIdx.x * blockDim.x + threadIdx.x;
    if (i < n) {
        int off = g_scan[arr][i] - g_cnt[arr][i] + g_psum_ex[arr][i >> 10];
        g_off[arr][i] = off;
        g_cur[arr][i] = off;
        g_cnt[arr][i] = 0;    // restore invariant for the next kernel_launch call
    }
}

// ---------------------------------------------------------------------------
// K5: build records for both CSRs (atom-sorted slots).
// Angular: 16B record, sw12 folded into fp16 valence products.
// Radial:  8B record, species folded into the integer part of sw.
// ---------------------------------------------------------------------------
__global__ void scatter_kernel(const float* __restrict__ angles,
                               const int*  __restrict__ central,
                               const int*  __restrict__ asrc,
                               const int*  __restrict__ adst,
                               const float* __restrict__ dist,
                               const float* __restrict__ sw,
                               const int*  __restrict__ esrc,
                               const int*  __restrict__ edst,
                               const int*  __restrict__ species,
                               int n_angles, int n_edges) {
    int t = blockIdx.x * blockDim.x + threadIdx.x;
    if (t < n_angles) {
        int es = asrc[t], ed = adst[t];
        float4 ps = g_eang[es];
        float4 pd = g_eang[ed];
        float d12  = 0.5f * (ps.x + pd.x);
        float sw12 = ps.y * pd.y;
        float ca   = __cosf(angles[t]);
        float vp0 = ps.z + pd.z, vp1 = ps.w + pd.w;
        float vm0 = ps.z * pd.z, vm1 = ps.w * pd.w;
        __half2 h01 = __floats2half2_rn(sw12 * vp0 * vm0, sw12 * vp0 * vm1);
        __half2 h23 = __floats2half2_rn(sw12 * vp1 * vm0, sw12 * vp1 * vm1);
        int pos = atomicAdd(&g_cur[0][central[t]], 1);
        float4 r;
        r.x = d12;
        r.y = ca;
        r.z = __uint_as_float(*reinterpret_cast<unsigned*>(&h01));
        r.w = __uint_as_float(*reinterpret_cast<unsigned*>(&h23));
        g_arec[pos] = r;
    }
    if (t < n_edges) {
        float d = dist[t], s = sw[t];
        int sd = species[edst[t]];
        int pos = atomicAdd(&g_cur[1][esrc[t]], 1);
        g_rrec[pos] = make_float2(d, (float)sd + s);
    }
}

// ---------------------------------------------------------------------------
// K6: fused accumulation. One warp per atom: radial in smem (conflict-free),
// angular in registers (static indices per lane). No atomics.
// ---------------------------------------------------------------------------
__device__ __forceinline__ float pick_val(float pz, float pw, int v) {
    unsigned u01 = __float_as_uint(pz);
    unsigned u23 = __float_as_uint(pw);
    __half2 h01 = *reinterpret_cast<__half2*>(&u01);
    __half2 h23 = *reinterpret_cast<__half2*>(&u23);
    float2 f01 = __half22float2(h01);
    float2 f23 = __half22float2(h23);
    float lo = (v & 2) ? f23.x : f01.x;
    float hi = (v & 2) ? f23.y : f01.y;
    return (v & 1) ? hi : lo;
}

__global__ void accum_kernel(float* __restrict__ out, int n_atoms) {
    __shared__ float sacc[8][2][16 * 17];
    int w    = threadIdx.x >> 5;
    int lane = threadIdx.x & 31;
    int atom = blockIdx.x * 8 + w;
    if (atom >= n_atoms) return;

    // ---- radial
    float* mybuf = &sacc[w][0][0];
    for (int k = lane; k < 2 * 16 * 17; k += 32) mybuf[k] = 0.f;
    __syncwarp();

    int hw = lane >> 4, lr = lane & 15;
    float ctr = STEP_R * (float)lr;
    float* hbuf = &sacc[w][hw][0];
    {
        int s0 = g_off[1][atom], e0 = g_off[1][atom + 1];
        for (int i = s0 + hw; i < e0; i += 2) {
            float2 r = g_rrec[i];
            int sd = (int)r.y;
            float s = r.y - (float)sd;
            float u = r.x - ctr;
            float v = s * __expf(-ETA_R * u * u);
            hbuf[lr * 17 + sd] += v;
        }
    }
    __syncwarp();
    {
        float* obase = out + (long)atom * ROW + RAD_OFF;
        #pragma unroll
        for (int k = 0; k < 8; k++) {
            int idx = k * 32 + lane;          // coalesced
            int r = idx >> 4, s = idx & 15;
            obase[idx] = sacc[w][0][r * 17 + s] + sacc[w][1][r * 17 + s];
        }
    }

    // ---- angular: lane owns (ra = lane>>2, v = lane&3), unrolled x4
    int ra = lane >> 2, v = lane & 3;
    float center = 0.5f * (float)ra;
    float a0 = 0.f, a1 = 0.f, a2 = 0.f, a3 = 0.f, a4 = 0.f;
    int s1 = g_off[0][atom], e1 = g_off[0][atom + 1];
    const float4* __restrict__ rec = g_arec;

    int i = s1;
    for (; i + 4 <= e1; i += 4) {
        float4 p = rec[i];
        float4 q = rec[i + 1];
        float4 r = rec[i + 2];
        float4 s = rec[i + 3];
        #pragma unroll
        for (int k = 0; k < 4; k++) {
            float4 c = (k == 0) ? p : (k == 1) ? q : (k == 2) ? r : s;
            float val = pick_val(c.z, c.w, v);
            float u  = c.x - center;
            float tt = __expf(-ETA2 * u * u) * val;
            float ca = c.y;
            float c2 = 2.0f * ca;
            float f2 = c2 * ca - 1.0f;
            float f3 = c2 * f2 - ca;
            float f4 = c2 * f3 - f2;
            a0 += tt;
            a1 = fmaf(ca, tt, a1);
            a2 = fmaf(f2, tt, a2);
            a3 = fmaf(f3, tt, a3);
            a4 = fmaf(f4, tt, a4);
        }
    }
    for (; i < e1; i++) {
        float4 c = rec[i];
        float val = pick_val(c.z, c.w, v);
        float u  = c.x - center;
        float tt = __expf(-ETA2 * u * u) * val;
        float ca = c.y;
        float c2 = 2.0f * ca;
        float f2 = c2 * ca - 1.0f;
        float f3 = c2 * f2 - ca;
        float f4 = c2 * f3 - f2;
        a0 += tt;
        a1 = fmaf(ca, tt, a1);
        a2 = fmaf(f2, tt, a2);
        a3 = fmaf(f3, tt, a3);
        a4 = fmaf(f4, tt, a4);
    }

    float* base = out + (long)atom * ROW + ANG_OFF + ra * 20 + v;
    base[0]  = a0;
    base[4]  = a1;
    base[8]  = a2;
    base[12] = a3;
    base[16] = a4;
}

// ---------------------------------------------------------------------------
// Launch
// ---------------------------------------------------------------------------
extern "C" void kernel_launch(void* const* d_in, const int* in_sizes, int n_in,
                              void* d_out, int out_size) {
    const int*   species      = (const int*)  d_in[0];
    const float* distances    = (const float*)d_in[1];
    const float* switch_      = (const float*)d_in[2];
    const int*   edge_src     = (const int*)  d_in[3];
    const int*   edge_dst     = (const int*)  d_in[4];
    const float* angles       = (const float*)d_in[5];
    const float* dang         = (const float*)d_in[6];
    const float* switch_ang   = (const float*)d_in[7];
    const int*   central_atom = (const int*)  d_in[8];
    const int*   angle_src    = (const int*)  d_in[9];
    const int*   angle_dst    = (const int*)  d_in[10];
    const int*   edge_dst_ang = (const int*)  d_in[11];
    const float* valence_tab  = (const float*)d_in[12];

    float* out = (float*)d_out;

    int n_atoms     = in_sizes[0];
    int n_edges     = in_sizes[1];
    int n_angles    = in_sizes[5];
    int n_edges_ang = in_sizes[6];

    // K1: prep + histograms (fused; counters are zero on entry by invariant)
    int n1 = n_angles > n_edges ? n_angles : n_edges;
    prep_hist_kernel<<<(n1 + 255) / 256, 256>>>(out, species, edge_dst_ang,
                                                valence_tab, dang, switch_ang,
                                                central_atom, edge_src,
                                                n_atoms, n_edges_ang,
                                                n_angles, n_edges);

    // K2-K4: scans (scan3 re-zeroes g_cnt for the next call)
    int nb = (n_atoms + 1023) / 1024;
    dim3 g1(nb, 2);
    scan1_kernel<<<g1, 1024>>>(n_atoms);
    scan2_kernel<<<1, 128>>>(nb, n_atoms);
    dim3 g3((n_atoms + 255) / 256, 2);
    scan3_kernel<<<g3, 256>>>(n_atoms);

    // K5: scatter records
    scatter_kernel<<<(n1 + 255) / 256, 256>>>(angles, central_atom,
                                              angle_src, angle_dst,
                                              distances, switch_, edge_src,
                                              edge_dst, species,
                                              n_angles, n_edges);

    // K6: fused accumulation (one warp per atom)
    accum_kernel<<<(n_atoms + 7) / 8, 256>>>(out, n_atoms);
}

// round 7
// speedup vs baseline: 3.1700x; 1.0462x over previous
#include <cuda_runtime.h>
#include <cuda_bf16.h>
#include <cuda_fp16.h>

// Problem constants (fixed by the reference)
#define NSPEC      16
#define DIMRAD     16
#define DIMRADANG  8
#define NF         5          // NMAX_ANGLE + 1
#define VDIM       2
#define ROW        432        // 16 + 256 + 160
#define RAD_OFF    16
#define ANG_OFF    272
#define MAX_EDGES      1000000
#define MAX_EDGES_ANG  500000
#define MAX_ANGLES     2000000
#define MAX_ATOMS      50000
#define NB_MAX         64

#define ETA_R  10.24f                 // (16/5)^2
#define STEP_R 0.33333333333333333f   // 5/15
#define ETA2   5.2244897959183673f    // (8/3.5)^2
#define KA    (-7.5373556525f)        // -ETA2  * log2(e)
#define KR    (-14.7731972231f)       // -ETA_R * log2(e)

// scratch (static __device__ — zero-initialized at module load, no runtime alloc)
__device__ float4 g_eang[MAX_EDGES_ANG];     // {d, sw, v0, v1} per angular edge
__device__ int    g_cnt[2][MAX_ATOMS];       // zero at kernel_launch entry (invariant)
__device__ int    g_off[2][MAX_ATOMS + 1];
__device__ int    g_cur[2][MAX_ATOMS];
__device__ unsigned g_look[2][NB_MAX];       // lookback channels; zero at entry (invariant)
__device__ int    g_done;                    // self-resetting
__device__ float4 g_arec[MAX_ANGLES];        // {d12, ca, half2(v0,v1), half2(v2,v3)}
__device__ float2 g_rrec[MAX_EDGES];         // {d, (float)sd + sw}

__device__ __forceinline__ float ex2f(float x) {
    float y;
    asm("ex2.approx.ftz.f32 %0, %1;" : "=f"(y) : "f"(x));
    return y;
}

// ---------------------------------------------------------------------------
// K1: prep (one-hot, packed angular-edge table) + both histograms, fused.
// ---------------------------------------------------------------------------
__global__ void prep_hist_kernel(float* __restrict__ out,
                                 const int* __restrict__ species,
                                 const int* __restrict__ edge_dst_ang,
                                 const float* __restrict__ vtab,
                                 const float* __restrict__ dang,
                                 const float* __restrict__ swang,
                                 const int* __restrict__ central,
                                 const int* __restrict__ esrc,
                                 int n_atoms, int n_edges_ang,
                                 int n_angles, int n_edges) {
    int i = blockIdx.x * blockDim.x + threadIdx.x;
    if (i < n_atoms) {
        float4* p = (float4*)(out + (long)i * ROW);
        float4 z = make_float4(0.f, 0.f, 0.f, 0.f);
        p[0] = z; p[1] = z; p[2] = z; p[3] = z;
        out[(long)i * ROW + species[i]] = 1.0f;
    }
    if (i < n_edges_ang) {
        int s = species[edge_dst_ang[i]];
        g_eang[i] = make_float4(dang[i], swang[i],
                                vtab[s * VDIM + 0], vtab[s * VDIM + 1]);
    }
    if (i < n_angles) atomicAdd(&g_cnt[0][central[i]], 1);
    if (i < n_edges)  atomicAdd(&g_cnt[1][esrc[i]], 1);
}

// ---------------------------------------------------------------------------
// K2: single-pass scan (decoupled lookback), both arrays packed in u64.
// Channel word: bits[31:30] flag (0=invalid,1=aggregate,2=prefix), [29:0] value.
// All blocks (<=49) fit in one wave -> lookback spin cannot deadlock.
// Resets g_cnt and g_look for the next call (zero invariant).
// ---------------------------------------------------------------------------
__global__ void scan_kernel(int n, int nb) {
    __shared__ unsigned long long ws[32];
    __shared__ unsigned long long s_base;
    int b = blockIdx.x, tid = threadIdx.x, lane = tid & 31, w = tid >> 5;
    int i = b * 1024 + tid;
    unsigned c0 = (i < n) ? (unsigned)g_cnt[0][i] : 0u;
    unsigned c1 = (i < n) ? (unsigned)g_cnt[1][i] : 0u;
    unsigned long long v = (unsigned long long)c0 | ((unsigned long long)c1 << 32);
    unsigned long long x = v;
    #pragma unroll
    for (int d = 1; d < 32; d <<= 1) {
        unsigned long long t = __shfl_up_sync(0xffffffffu, x, d);
        if (lane >= d) x += t;
    }
    if (lane == 31) ws[w] = x;
    __syncthreads();
    if (w == 0) {
        unsigned long long s = ws[lane];
        #pragma unroll
        for (int d = 1; d < 32; d <<= 1) {
            unsigned long long t = __shfl_up_sync(0xffffffffu, s, d);
            if (lane >= d) s += t;
        }
        ws[lane] = s;
    }
    __syncthreads();
    unsigned long long incl  = x + (w ? ws[w - 1] : 0);
    unsigned long long total = ws[31];

    if (tid == 0) {
        unsigned t0 = (unsigned)(total & 0xffffffffull);
        unsigned t1 = (unsigned)(total >> 32);
        unsigned run0 = 0, run1 = 0;
        if (b == 0) {
            ((volatile unsigned*)g_look[0])[0] = (2u << 30) | t0;
            ((volatile unsigned*)g_look[1])[0] = (2u << 30) | t1;
        } else {
            ((volatile unsigned*)g_look[0])[b] = (1u << 30) | t0;
            ((volatile unsigned*)g_look[1])[b] = (1u << 30) | t1;
            #pragma unroll 1
            for (int ch = 0; ch < 2; ch++) {
                unsigned run = 0;
                int j = b - 1;
                while (true) {
                    unsigned s = ((volatile unsigned*)g_look[ch])[j];
                    unsigned f = s >> 30;
                    if (f == 0u) continue;          // spin until published
                    run += s & 0x3fffffffu;
                    if (f == 2u) break;             // hit a full prefix
                    j--;
                }
                if (ch == 0) run0 = run; else run1 = run;
            }
            ((volatile unsigned*)g_look[0])[b] = (2u << 30) | (run0 + t0);
            ((volatile unsigned*)g_look[1])[b] = (2u << 30) | (run1 + t1);
        }
        s_base = (unsigned long long)run0 | ((unsigned long long)run1 << 32);
    }
    __syncthreads();
    unsigned long long base = s_base;
    if (i < n) {
        int off0 = (int)((unsigned)(base & 0xffffffffull) + (unsigned)(incl & 0xffffffffull) - c0);
        int off1 = (int)((unsigned)(base >> 32) + (unsigned)(incl >> 32) - c1);
        g_off[0][i] = off0; g_cur[0][i] = off0; g_cnt[0][i] = 0;
        g_off[1][i] = off1; g_cur[1][i] = off1; g_cnt[1][i] = 0;
        if (i == n - 1) {
            g_off[0][n] = off0 + (int)c0;
            g_off[1][n] = off1 + (int)c1;
        }
    }
    if (tid == 0) {
        __threadfence();
        int d = atomicAdd(&g_done, 1);
        if (d == nb - 1) {               // last block: reset lookback state
            for (int j = 0; j < nb; j++) { g_look[0][j] = 0u; g_look[1][j] = 0u; }
            g_done = 0;
        }
    }
}

// ---------------------------------------------------------------------------
// K3: build records for both CSRs (atom-sorted slots).
// ---------------------------------------------------------------------------
__global__ void scatter_kernel(const float* __restrict__ angles,
                               const int*  __restrict__ central,
                               const int*  __restrict__ asrc,
                               const int*  __restrict__ adst,
                               const float* __restrict__ dist,
                               const float* __restrict__ sw,
                               const int*  __restrict__ esrc,
                               const int*  __restrict__ edst,
                               const int*  __restrict__ species,
                               int n_angles, int n_edges) {
    int t = blockIdx.x * blockDim.x + threadIdx.x;
    if (t < n_angles) {
        int es = asrc[t], ed = adst[t];
        float4 ps = g_eang[es];
        float4 pd = g_eang[ed];
        float d12  = 0.5f * (ps.x + pd.x);
        float sw12 = ps.y * pd.y;
        float ca   = __cosf(angles[t]);
        float vp0 = ps.z + pd.z, vp1 = ps.w + pd.w;
        float vm0 = ps.z * pd.z, vm1 = ps.w * pd.w;
        __half2 h01 = __floats2half2_rn(sw12 * vp0 * vm0, sw12 * vp0 * vm1);
        __half2 h23 = __floats2half2_rn(sw12 * vp1 * vm0, sw12 * vp1 * vm1);
        int pos = atomicAdd(&g_cur[0][central[t]], 1);
        float4 r;
        r.x = d12;
        r.y = ca;
        r.z = __uint_as_float(*reinterpret_cast<unsigned*>(&h01));
        r.w = __uint_as_float(*reinterpret_cast<unsigned*>(&h23));
        g_arec[pos] = r;
    }
    if (t < n_edges) {
        float d = dist[t], s = sw[t];
        int sd = species[edst[t]];
        int pos = atomicAdd(&g_cur[1][esrc[t]], 1);
        g_rrec[pos] = make_float2(d, (float)sd + s);
    }
}

// ---------------------------------------------------------------------------
// K4: fused accumulation. One warp per atom; no atomics.
// ---------------------------------------------------------------------------
__device__ __forceinline__ float pick_val(float pz, float pw, int v) {
    unsigned u = (v & 2) ? __float_as_uint(pw) : __float_as_uint(pz);
    unsigned short h = (unsigned short)(u >> ((v & 1) << 4));
    return __half2float(__ushort_as_half(h));
}

__global__ void accum_kernel(float* __restrict__ out, int n_atoms) {
    __shared__ float sacc[8][2][16 * 17];
    int w    = threadIdx.x >> 5;
    int lane = threadIdx.x & 31;
    int atom = blockIdx.x * 8 + w;
    if (atom >= n_atoms) return;

    // ---- radial
    float* mybuf = &sacc[w][0][0];
    for (int k = lane; k < 2 * 16 * 17; k += 32) mybuf[k] = 0.f;
    __syncwarp();

    int hw = lane >> 4, lr = lane & 15;
    float ctr = STEP_R * (float)lr;
    float* hbuf = &sacc[w][hw][0];
    {
        int s0 = g_off[1][atom], e0 = g_off[1][atom + 1];
        for (int i = s0 + hw; i < e0; i += 2) {
            float2 r = g_rrec[i];
            int sd = (int)r.y;
            float s = r.y - (float)sd;
            float u = r.x - ctr;
            float v = s * ex2f(KR * u * u);
            hbuf[lr * 17 + sd] += v;
        }
    }
    __syncwarp();
    {
        float* obase = out + (long)atom * ROW + RAD_OFF;
        #pragma unroll
        for (int k = 0; k < 8; k++) {
            int idx = k * 32 + lane;          // coalesced
            int r = idx >> 4, s = idx & 15;
            obase[idx] = sacc[w][0][r * 17 + s] + sacc[w][1][r * 17 + s];
        }
    }

    // ---- angular: lane owns (ra = lane>>2, v = lane&3), unrolled x4
    int ra = lane >> 2, v = lane & 3;
    float center = 0.5f * (float)ra;
    float a0 = 0.f, a1 = 0.f, a2 = 0.f, a3 = 0.f, a4 = 0.f;
    int s1 = g_off[0][atom], e1 = g_off[0][atom + 1];
    const float4* __restrict__ rec = g_arec;

    int i = s1;
    for (; i + 4 <= e1; i += 4) {
        float4 p = rec[i];
        float4 q = rec[i + 1];
        float4 r = rec[i + 2];
        float4 s = rec[i + 3];
        #pragma unroll
        for (int k = 0; k < 4; k++) {
            float4 c = (k == 0) ? p : (k == 1) ? q : (k == 2) ? r : s;
            float val = pick_val(c.z, c.w, v);
            float u  = c.x - center;
            float tt = ex2f(KA * u * u) * val;
            float ca = c.y;
            float c2 = 2.0f * ca;
            float f2 = c2 * ca - 1.0f;
            float f3 = c2 * f2 - ca;
            float f4 = c2 * f3 - f2;
            a0 += tt;
            a1 = fmaf(ca, tt, a1);
            a2 = fmaf(f2, tt, a2);
            a3 = fmaf(f3, tt, a3);
            a4 = fmaf(f4, tt, a4);
        }
    }
    for (; i < e1; i++) {
        float4 c = rec[i];
        float val = pick_val(c.z, c.w, v);
        float u  = c.x - center;
        float tt = ex2f(KA * u * u) * val;
        float ca = c.y;
        float c2 = 2.0f * ca;
        float f2 = c2 * ca - 1.0f;
        float f3 = c2 * f2 - ca;
        float f4 = c2 * f3 - f2;
        a0 += tt;
        a1 = fmaf(ca, tt, a1);
        a2 = fmaf(f2, tt, a2);
        a3 = fmaf(f3, tt, a3);
        a4 = fmaf(f4, tt, a4);
    }

    float* base = out + (long)atom * ROW + ANG_OFF + ra * 20 + v;
    base[0]  = a0;
    base[4]  = a1;
    base[8]  = a2;
    base[12] = a3;
    base[16] = a4;
}

// ---------------------------------------------------------------------------
// Launch
// ---------------------------------------------------------------------------
extern "C" void kernel_launch(void* const* d_in, const int* in_sizes, int n_in,
                              void* d_out, int out_size) {
    const int*   species      = (const int*)  d_in[0];
    const float* distances    = (const float*)d_in[1];
    const float* switch_      = (const float*)d_in[2];
    const int*   edge_src     = (const int*)  d_in[3];
    const int*   edge_dst     = (const int*)  d_in[4];
    const float* angles       = (const float*)d_in[5];
    const float* dang         = (const float*)d_in[6];
    const float* switch_ang   = (const float*)d_in[7];
    const int*   central_atom = (const int*)  d_in[8];
    const int*   angle_src    = (const int*)  d_in[9];
    const int*   angle_dst    = (const int*)  d_in[10];
    const int*   edge_dst_ang = (const int*)  d_in[11];
    const float* valence_tab  = (const float*)d_in[12];

    float* out = (float*)d_out;

    int n_atoms     = in_sizes[0];
    int n_edges     = in_sizes[1];
    int n_angles    = in_sizes[5];
    int n_edges_ang = in_sizes[6];

    // K1: prep + histograms (fused; counters zero on entry by invariant)
    int n1 = n_angles > n_edges ? n_angles : n_edges;
    prep_hist_kernel<<<(n1 + 255) / 256, 256>>>(out, species, edge_dst_ang,
                                                valence_tab, dang, switch_ang,
                                                central_atom, edge_src,
                                                n_atoms, n_edges_ang,
                                                n_angles, n_edges);

    // K2: single-pass decoupled-lookback scan (re-zeroes g_cnt / g_look)
    int nb = (n_atoms + 1023) / 1024;
    scan_kernel<<<nb, 1024>>>(n_atoms, nb);

    // K3: scatter records
    scatter_kernel<<<(n1 + 255) / 256, 256>>>(angles, central_atom,
                                              angle_src, angle_dst,
                                              distances, switch_, edge_src,
                                              edge_dst, species,
                                              n_angles, n_edges);

    // K4: fused accumulation (one warp per atom)
    accum_kernel<<<(n_atoms + 7) / 8, 256>>>(out, n_atoms);
}